// round 10
// baseline (speedup 1.0000x reference)
#include <cuda_runtime.h>
#include <cuda_bf16.h>
#include <cuda_fp16.h>
#include <cstdint>

// ---------------------------------------------------------------------------
// Shapes (fixed by the problem)
// ---------------------------------------------------------------------------
#define B_  16
#define N_  4096
#define C_  768
#define L_  16
#define H_  12
#define HD_ 64
#define STEPS_ 3
#define BH_ (B_ * H_)               // 192

#define MROWS_ (B_ * N_)            // 65536
#define KSEG_  2                    // xh*wh, xl*wh  (fp16 2-term)
#define BK_    64
#define CH_PER_SEG_ (C_ / BK_)      // 12
#define NCHUNK_TOT_ (KSEG_ * CH_PER_SEG_)  // 24

// Hopfield split
#define TN_ 128
#define NWARP_ 8
#define NS_ 8
#define NT_SPL_ (N_ / NS_ / TN_)    // 4 tiles per split

// ---------------------------------------------------------------------------
// Scratch (__device__ globals)
// ---------------------------------------------------------------------------
__device__ __align__(16) __nv_bfloat16 g_kh[(size_t)BH_ * N_ * HD_];
__device__ __align__(16) __nv_bfloat16 g_kl[(size_t)BH_ * N_ * HD_];
__device__ __align__(16) __half g_xh16[(size_t)MROWS_ * C_];
__device__ __align__(16) __half g_xl16[(size_t)MROWS_ * C_];
__device__ __align__(16) __half g_wh16[(size_t)C_ * C_];
__device__ float g_q0_scr[L_ * C_];
__device__ float g_qf_scr[B_ * L_ * C_];
__device__ float g_tmp_scr[B_ * L_ * C_];
__device__ __align__(16) float g_q_state[BH_ * L_ * HD_];
__device__ float g_m_part[BH_ * NS_ * L_];
__device__ float g_z_part[BH_ * NS_ * L_];
__device__ __align__(16) float g_acc_part[(size_t)BH_ * NS_ * L_ * HD_];

// ---------------------------------------------------------------------------
// helpers
// ---------------------------------------------------------------------------
__device__ __forceinline__ uint32_t smem_u32(const void* p) {
    uint32_t a;
    asm("{ .reg .u64 t; cvta.to.shared.u64 t, %1; cvt.u32.u64 %0, t; }" : "=r"(a) : "l"(p));
    return a;
}
__device__ __forceinline__ void cpa16(uint32_t dst, const void* src) {
    asm volatile("cp.async.cg.shared.global [%0], [%1], 16;" :: "r"(dst), "l"(src));
}
#define CP_COMMIT() asm volatile("cp.async.commit_group;" ::: "memory")
#define CP_WAIT1()  asm volatile("cp.async.wait_group 1;" ::: "memory")
#define CP_WAIT0()  asm volatile("cp.async.wait_group 0;" ::: "memory")

__device__ __forceinline__ void ldsm_x4(uint32_t* r, uint32_t addr) {
    asm volatile("ldmatrix.sync.aligned.m8n8.x4.shared.b16 {%0,%1,%2,%3}, [%4];"
                 : "=r"(r[0]), "=r"(r[1]), "=r"(r[2]), "=r"(r[3]) : "r"(addr));
}
__device__ __forceinline__ void ldsm_x4t(uint32_t* r, uint32_t addr) {
    asm volatile("ldmatrix.sync.aligned.m8n8.x4.trans.shared.b16 {%0,%1,%2,%3}, [%4];"
                 : "=r"(r[0]), "=r"(r[1]), "=r"(r[2]), "=r"(r[3]) : "r"(addr));
}
__device__ __forceinline__ void mma_bf16(float* d, const uint32_t* a, const uint32_t* b) {
    asm volatile(
        "mma.sync.aligned.m16n8k16.row.col.f32.bf16.bf16.f32 "
        "{%0,%1,%2,%3}, {%4,%5,%6,%7}, {%8,%9}, {%0,%1,%2,%3};"
        : "+f"(d[0]), "+f"(d[1]), "+f"(d[2]), "+f"(d[3])
        : "r"(a[0]), "r"(a[1]), "r"(a[2]), "r"(a[3]), "r"(b[0]), "r"(b[1]));
}
__device__ __forceinline__ void mma_fp16(float* d, const uint32_t* a, const uint32_t* b) {
    asm volatile(
        "mma.sync.aligned.m16n8k16.row.col.f32.f16.f16.f32 "
        "{%0,%1,%2,%3}, {%4,%5,%6,%7}, {%8,%9}, {%0,%1,%2,%3};"
        : "+f"(d[0]), "+f"(d[1]), "+f"(d[2]), "+f"(d[3])
        : "r"(a[0]), "r"(a[1]), "r"(a[2]), "r"(a[3]), "r"(b[0]), "r"(b[1]));
}
__device__ __forceinline__ void split2(float a, float b, uint32_t* hi, uint32_t* lo) {
    __nv_bfloat16 ha = __float2bfloat16(a), hb = __float2bfloat16(b);
    __nv_bfloat16 la = __float2bfloat16(a - __bfloat162float(ha));
    __nv_bfloat16 lb = __float2bfloat16(b - __bfloat162float(hb));
    *hi = (uint32_t)__bfloat16_as_ushort(ha) | ((uint32_t)__bfloat16_as_ushort(hb) << 16);
    *lo = (uint32_t)__bfloat16_as_ushort(la) | ((uint32_t)__bfloat16_as_ushort(lb) << 16);
}
__device__ __forceinline__ void split2h(float a, float b, uint32_t* hi, uint32_t* lo) {
    __half ha = __float2half(a), hb = __float2half(b);
    __half la = __float2half(a - __half2float(ha));
    __half lb = __float2half(b - __half2float(hb));
    *hi = (uint32_t)__half_as_ushort(ha) | ((uint32_t)__half_as_ushort(hb) << 16);
    *lo = (uint32_t)__half_as_ushort(la) | ((uint32_t)__half_as_ushort(lb) << 16);
}

// ---------------------------------------------------------------------------
// Kernel A1: split fp32 -> (hi, lo) fp16 pair (for x)
// ---------------------------------------------------------------------------
__global__ void __launch_bounds__(256) convert_split_fp16(
    const float* __restrict__ src, __half* __restrict__ hi,
    __half* __restrict__ lo, int nchunks)
{
    int idx = blockIdx.x * 256 + threadIdx.x;
    if (idx >= nchunks) return;
    size_t e = (size_t)idx * 8;

    const float4* p = (const float4*)(src + e);
    float4 a = p[0], b = p[1];
    float v[8] = {a.x, a.y, a.z, a.w, b.x, b.y, b.z, b.w};

    uint32_t hp[4], lp[4];
#pragma unroll
    for (int i = 0; i < 4; i++) split2h(v[2*i], v[2*i+1], &hp[i], &lp[i]);
    *(uint4*)(hi + e) = make_uint4(hp[0], hp[1], hp[2], hp[3]);
    *(uint4*)(lo + e) = make_uint4(lp[0], lp[1], lp[2], lp[3]);
}

// Kernel A2: fp32 -> fp16 (for W)
__global__ void __launch_bounds__(256) convert_fp16(
    const float* __restrict__ src, __half* __restrict__ dst, int nchunks)
{
    int idx = blockIdx.x * 256 + threadIdx.x;
    if (idx >= nchunks) return;
    size_t e = (size_t)idx * 8;
    const float4* p = (const float4*)(src + e);
    float4 a = p[0], b = p[1];
    float v[8] = {a.x, a.y, a.z, a.w, b.x, b.y, b.z, b.w};
    uint32_t o[4];
#pragma unroll
    for (int i = 0; i < 4; i++) {
        __half h0 = __float2half(v[2*i]), h1 = __float2half(v[2*i+1]);
        o[i] = (uint32_t)__half_as_ushort(h0) | ((uint32_t)__half_as_ushort(h1) << 16);
    }
    *(uint4*)(dst + e) = make_uint4(o[0], o[1], o[2], o[3]);
}

// ---------------------------------------------------------------------------
// Kernel B: HMMA GEMM  k = X @ Wk^T  (K = 2*768, fp16 2-term)  (unchanged)
// ---------------------------------------------------------------------------
#define KTB_ 16384
#define STAGEB_ (2 * KTB_)
#define NSTG_ 3
#define GEMM_SMEM_REQ (NSTG_ * STAGEB_)  // 98304
#define GT_ 128

__device__ __forceinline__ void load_tile64(
    uint32_t aS, uint32_t bS, const char* Aseg, const char* Bseg,
    int mt, int nt, int kk, int tid)
{
#pragma unroll
    for (int i = 0; i < 8; i++) {
        int idx = tid + i * GT_;
        int row = idx >> 3, c = idx & 7;
        uint32_t sw = (uint32_t)((c ^ (row & 7)) * 16);
        cpa16(aS + row * 128 + sw,
              Aseg + ((size_t)(mt * 128 + row) * C_ + kk + c * 8) * 2);
    }
#pragma unroll
    for (int i = 0; i < 8; i++) {
        int idx = tid + i * GT_;
        int row = idx >> 3, c = idx & 7;
        uint32_t sw = (uint32_t)((c ^ (row & 7)) * 16);
        cpa16(bS + row * 128 + sw,
              Bseg + ((size_t)(nt * 128 + row) * C_ + kk + c * 8) * 2);
    }
}

struct Frag { uint32_t a[4][4]; uint32_t b[4][4]; };

__device__ __forceinline__ void load_frag(
    Frag& f, uint32_t aS, uint32_t bS, int h,
    int wm, int wn, int arow_l, int agrp_l, int brow_l, int bgrp_l)
{
#pragma unroll
    for (int mi = 0; mi < 4; mi++) {
        int row = wm * 64 + mi * 16 + arow_l;
        int g   = (2 * h + agrp_l) ^ (row & 7);
        ldsm_x4(f.a[mi], aS + row * 128 + g * 16);
    }
#pragma unroll
    for (int p = 0; p < 4; p++) {
        int row = wn * 64 + p * 16 + brow_l;
        int g   = (2 * h + bgrp_l) ^ (row & 7);
        ldsm_x4(f.b[p], bS + row * 128 + g * 16);
    }
}

__global__ void __launch_bounds__(GT_, 2) k_gemm_mma(
    const __half* __restrict__ xh, const __half* __restrict__ xl,
    const __half* __restrict__ wh,
    __nv_bfloat16* __restrict__ khg, __nv_bfloat16* __restrict__ klg)
{
    extern __shared__ char dsm[];
    const uint32_t sbase = smem_u32(dsm);

    const int tid  = threadIdx.x;
    const int lane = tid & 31;
    const int warp = tid >> 5;
    const int wm   = warp >> 1;
    const int wn   = warp & 1;
    const int nt   = blockIdx.x;
    const int mt   = blockIdx.y;

    const char* Asrc[KSEG_] = {(const char*)xh, (const char*)xl};
    const char* Bsrc[KSEG_] = {(const char*)wh, (const char*)wh};

    float acc[4][8][4];
#pragma unroll
    for (int mi = 0; mi < 4; mi++)
#pragma unroll
        for (int ni = 0; ni < 8; ni++)
#pragma unroll
            for (int i = 0; i < 4; i++) acc[mi][ni][i] = 0.0f;

#pragma unroll
    for (int s = 0; s < NSTG_ - 1; s++) {
        load_tile64(sbase + s * STAGEB_, sbase + s * STAGEB_ + KTB_,
                    Asrc[0], Bsrc[0], mt, nt, s * BK_, tid);
        CP_COMMIT();
    }

    const int arow_l = lane & 15;
    const int agrp_l = lane >> 4;
    const int brow_l = (lane & 7) + ((lane >> 4) & 1) * 8;
    const int bgrp_l = (lane >> 3) & 1;

    Frag fr[2];

    for (int kc = 0; kc < NCHUNK_TOT_; kc++) {
        CP_WAIT1();
        __syncthreads();

        int pf = kc + NSTG_ - 1;
        if (pf < NCHUNK_TOT_) {
            int seg = pf / CH_PER_SEG_;
            int kk  = (pf % CH_PER_SEG_) * BK_;
            int s   = pf % NSTG_;
            load_tile64(sbase + s * STAGEB_, sbase + s * STAGEB_ + KTB_,
                        Asrc[seg], Bsrc[seg], mt, nt, kk, tid);
        }
        CP_COMMIT();

        const uint32_t aS = sbase + (kc % NSTG_) * STAGEB_;
        const uint32_t bS = aS + KTB_;

        load_frag(fr[0], aS, bS, 0, wm, wn, arow_l, agrp_l, brow_l, bgrp_l);
#pragma unroll
        for (int h = 0; h < 4; h++) {
            if (h < 3)
                load_frag(fr[(h + 1) & 1], aS, bS, h + 1,
                          wm, wn, arow_l, agrp_l, brow_l, bgrp_l);
            const Frag& f = fr[h & 1];
#pragma unroll
            for (int mi = 0; mi < 4; mi++)
#pragma unroll
                for (int ni = 0; ni < 8; ni++)
                    mma_fp16(acc[mi][ni], f.a[mi], f.b[ni >> 1] + (ni & 1) * 2);
        }
    }

    // epilogue: split to bf16 hi/lo, scatter head-major [B, H, N, 64]
#pragma unroll
    for (int mi = 0; mi < 4; mi++) {
#pragma unroll
        for (int ni = 0; ni < 8; ni++) {
            int r = mt * 128 + wm * 64 + mi * 16 + (lane >> 2);
            int c = nt * 128 + wn * 64 + ni * 8 + (lane & 3) * 2;
            int b = r >> 12, n = r & (N_ - 1);
            int hh = c >> 6, d = c & 63;
            size_t addr = (((size_t)b * H_ + hh) * N_ + n) * HD_ + d;
            uint32_t h01, l01, h23, l23;
            split2(acc[mi][ni][0], acc[mi][ni][1], &h01, &l01);
            split2(acc[mi][ni][2], acc[mi][ni][3], &h23, &l23);
            *(uint32_t*)&khg[addr] = h01;
            *(uint32_t*)&klg[addr] = l01;
            *(uint32_t*)&khg[addr + 8 * HD_] = h23;
            *(uint32_t*)&klg[addr + 8 * HD_] = l23;
        }
    }
}

// ---------------------------------------------------------------------------
// Kernel 2: small GEMM  C[M,N] = A[M,K]*B[N,K]^T (+bias), BK=64 (unchanged)
// ---------------------------------------------------------------------------
__global__ void __launch_bounds__(256) small_gemm_nt(
    const float* __restrict__ A, const float* __restrict__ Bm,
    const float* __restrict__ bias, float* __restrict__ C,
    int M, int N, int K)
{
    __shared__ float AsT[64][17];
    __shared__ float BsT[64][65];

    const int t  = threadIdx.x;
    const int n0 = blockIdx.x * 64;
    const int m0 = blockIdx.y * 16;
    const int r0 = t >> 6;
    const int c  = t & 63;

    float acc[4] = {0.f, 0.f, 0.f, 0.f};

    for (int k0 = 0; k0 < K; k0 += 64) {
        __syncthreads();
        { int mm = t >> 4, k4 = (t & 15) * 4;
          float4 v = *(const float4*)&A[(long)(m0 + mm) * K + k0 + k4];
          AsT[k4 + 0][mm] = v.x; AsT[k4 + 1][mm] = v.y;
          AsT[k4 + 2][mm] = v.z; AsT[k4 + 3][mm] = v.w; }
        {
#pragma unroll
            for (int i = 0; i < 4; i++) {
                int idx = t + i * 256;
                int nn = idx >> 4, k4 = (idx & 15) * 4;
                float4 v = *(const float4*)&Bm[(long)(n0 + nn) * K + k0 + k4];
                BsT[k4 + 0][nn] = v.x; BsT[k4 + 1][nn] = v.y;
                BsT[k4 + 2][nn] = v.z; BsT[k4 + 3][nn] = v.w;
            }
        }
        __syncthreads();
#pragma unroll
        for (int kk = 0; kk < 64; kk++) {
            float bb = BsT[kk][c];
            acc[0] = fmaf(AsT[kk][r0 +  0], bb, acc[0]);
            acc[1] = fmaf(AsT[kk][r0 +  4], bb, acc[1]);
            acc[2] = fmaf(AsT[kk][r0 +  8], bb, acc[2]);
            acc[3] = fmaf(AsT[kk][r0 + 12], bb, acc[3]);
        }
    }
    float bv = bias ? bias[n0 + c] : 0.0f;
#pragma unroll
    for (int i = 0; i < 4; i++)
        C[(long)(m0 + r0 + 4 * i) * N + n0 + c] = acc[i] + bv;
}

// ---------------------------------------------------------------------------
// Hopfield step via HMMA, split-N (NS=8), q fragments hoisted to registers.
// ---------------------------------------------------------------------------
__global__ void hop_init_q(const float* __restrict__ q0, float* __restrict__ qst)
{
    int bh = blockIdx.x, h = bh % H_;
    for (int i = threadIdx.x; i < L_ * HD_; i += 256) {
        int l = i >> 6, d = i & 63;
        qst[bh * (L_ * HD_) + i] = q0[l * C_ + h * HD_ + d];
    }
}

#define KROW_ 144
#define KTILE_PAD_ (128 * KROW_)
#define HOP_SMEM_ (4 * KTILE_PAD_ + 2 * L_ * KROW_)   // 78336

__global__ void __launch_bounds__(256, 2) hop_partial(
    const float* __restrict__ qst,
    const __nv_bfloat16* __restrict__ khg, const __nv_bfloat16* __restrict__ klg,
    float* __restrict__ m_part, float* __restrict__ z_part,
    float* __restrict__ acc_part)
{
    extern __shared__ __align__(16) char hsm8[];
    __shared__ float mw[NWARP_][L_];
    __shared__ float zw[NWARP_][L_];
    __shared__ float Mg[L_];

    const int t     = threadIdx.x;
    const int warp  = t >> 5;
    const int lane  = t & 31;
    const int split = blockIdx.x;
    const int bh    = blockIdx.y;
    const uint32_t sb  = smem_u32(hsm8);
    const uint32_t KH0 = sb;
    const uint32_t KL0 = sb + 2 * KTILE_PAD_;
    const uint32_t QHo = sb + 4 * KTILE_PAD_;
    const uint32_t QLo = QHo + L_ * KROW_;

    const char* ksrc_h = (const char*)(khg + ((size_t)bh * N_ + split * (N_ / NS_)) * HD_);
    const char* ksrc_l = (const char*)(klg + ((size_t)bh * N_ + split * (N_ / NS_)) * HD_);

    // prefetch tile 0
#pragma unroll
    for (int i = 0; i < 4; i++) {
        int idx = t + i * 256;
        int row = idx >> 3, c = idx & 7;
        cpa16(KH0 + row * KROW_ + c * 16, ksrc_h + (size_t)idx * 16);
        cpa16(KL0 + row * KROW_ + c * 16, ksrc_l + (size_t)idx * 16);
    }
    CP_COMMIT();

    // q: scale, split, park in padded smem
    {
        float4 v = ((const float4*)(qst + bh * (L_ * HD_)))[t];
        int e = t * 4, r = e >> 6, d = e & 63;
        uint32_t h01, l01, h23, l23;
        split2(v.x * 0.125f, v.y * 0.125f, &h01, &l01);
        split2(v.z * 0.125f, v.w * 0.125f, &h23, &l23);
        char* qh = hsm8 + 4 * KTILE_PAD_ + r * KROW_ + d * 2;
        char* ql = qh + L_ * KROW_;
        *(uint32_t*)qh = h01; *(uint32_t*)(qh + 4) = h23;
        *(uint32_t*)ql = l01; *(uint32_t*)(ql + 4) = l23;
    }
    __syncthreads();   // q visible to all warps

    // hoist q fragments (loop-invariant across tiles)
    const uint32_t qa_off = (uint32_t)((lane & 15) * KROW_ + (lane >> 4) * 16);
    uint32_t qfh[4][4], qfl[4][4];
#pragma unroll
    for (int kc = 0; kc < 4; kc++) {
        ldsm_x4(qfh[kc], QHo + qa_off + kc * 32);
        ldsm_x4(qfl[kc], QLo + qa_off + kc * 32);
    }

    float S[2][4], O[8][4];
#pragma unroll
    for (int i = 0; i < 8; i++)
#pragma unroll
        for (int j = 0; j < 4; j++) O[i][j] = 0.0f;
    float m0 = -1e30f, m1 = -1e30f, Z0 = 0.0f, Z1 = 0.0f;

    const uint32_t kb_off = (uint32_t)((warp * 16 + ((lane >> 4) & 1) * 8 + (lane & 7)) * KROW_
                                       + ((lane >> 3) & 1) * 16);
    const uint32_t v_off  = (uint32_t)((warp * 16 + (lane & 15)) * KROW_ + (lane >> 4) * 16);

    for (int tile = 0; tile < NT_SPL_; tile++) {
        if (tile + 1 < NT_SPL_) {
            uint32_t khd = KH0 + ((tile + 1) & 1) * KTILE_PAD_;
            uint32_t kld = KL0 + ((tile + 1) & 1) * KTILE_PAD_;
            const char* sh = ksrc_h + (size_t)(tile + 1) * (TN_ * HD_ * 2);
            const char* sl = ksrc_l + (size_t)(tile + 1) * (TN_ * HD_ * 2);
#pragma unroll
            for (int i = 0; i < 4; i++) {
                int idx = t + i * 256;
                int row = idx >> 3, c = idx & 7;
                cpa16(khd + row * KROW_ + c * 16, sh + (size_t)idx * 16);
                cpa16(kld + row * KROW_ + c * 16, sl + (size_t)idx * 16);
            }
            CP_COMMIT();
            CP_WAIT1();
        } else {
            CP_WAIT0();
        }
        __syncthreads();

        const uint32_t khb = KH0 + (tile & 1) * KTILE_PAD_;
        const uint32_t klb = KL0 + (tile & 1) * KTILE_PAD_;

        // ---- scores: 3-term split, q from registers ----
#pragma unroll
        for (int nt = 0; nt < 2; nt++)
#pragma unroll
            for (int i = 0; i < 4; i++) S[nt][i] = 0.0f;
#pragma unroll
        for (int kc = 0; kc < 4; kc++) {
            uint32_t bh4[4], bl4[4];
            ldsm_x4(bh4, khb + kb_off + kc * 32);
            ldsm_x4(bl4, klb + kb_off + kc * 32);
            mma_bf16(S[0], qfh[kc], bh4);
            mma_bf16(S[1], qfh[kc], bh4 + 2);
            mma_bf16(S[0], qfh[kc], bl4);
            mma_bf16(S[1], qfh[kc], bl4 + 2);
            mma_bf16(S[0], qfl[kc], bh4);
            mma_bf16(S[1], qfl[kc], bh4 + 2);
        }

        // ---- online softmax ----
        float mx0 = fmaxf(fmaxf(S[0][0], S[0][1]), fmaxf(S[1][0], S[1][1]));
        float mx1 = fmaxf(fmaxf(S[0][2], S[0][3]), fmaxf(S[1][2], S[1][3]));
        mx0 = fmaxf(mx0, __shfl_xor_sync(0xffffffffu, mx0, 1));
        mx0 = fmaxf(mx0, __shfl_xor_sync(0xffffffffu, mx0, 2));
        mx1 = fmaxf(mx1, __shfl_xor_sync(0xffffffffu, mx1, 1));
        mx1 = fmaxf(mx1, __shfl_xor_sync(0xffffffffu, mx1, 2));
        float mn0 = fmaxf(m0, mx0), mn1 = fmaxf(m1, mx1);
        float f0 = __expf(m0 - mn0), f1 = __expf(m1 - mn1);
        Z0 *= f0; Z1 *= f1;
#pragma unroll
        for (int nt = 0; nt < 8; nt++) {
            O[nt][0] *= f0; O[nt][1] *= f0;
            O[nt][2] *= f1; O[nt][3] *= f1;
        }
        float P00 = __expf(S[0][0] - mn0), P01 = __expf(S[0][1] - mn0);
        float P02 = __expf(S[0][2] - mn1), P03 = __expf(S[0][3] - mn1);
        float P10 = __expf(S[1][0] - mn0), P11 = __expf(S[1][1] - mn0);
        float P12 = __expf(S[1][2] - mn1), P13 = __expf(S[1][3] - mn1);
        Z0 += P00 + P01 + P10 + P11;
        Z1 += P02 + P03 + P12 + P13;
        uint32_t ph[4], pl[4];
        split2(P00, P01, &ph[0], &pl[0]);
        split2(P02, P03, &ph[1], &pl[1]);
        split2(P10, P11, &ph[2], &pl[2]);
        split2(P12, P13, &ph[3], &pl[3]);
        m0 = mn0; m1 = mn1;

        // ---- AV ----
#pragma unroll
        for (int hp = 0; hp < 4; hp++) {
            uint32_t vh4[4], vl4[4];
            ldsm_x4t(vh4, khb + v_off + hp * 32);
            ldsm_x4t(vl4, klb + v_off + hp * 32);
            mma_bf16(O[2*hp],     ph, vh4);
            mma_bf16(O[2*hp],     ph, vl4);
            mma_bf16(O[2*hp],     pl, vh4);
            mma_bf16(O[2*hp + 1], ph, vh4 + 2);
            mma_bf16(O[2*hp + 1], ph, vl4 + 2);
            mma_bf16(O[2*hp + 1], pl, vh4 + 2);
        }
        __syncthreads();
    }

    // ---- block combine ----
    Z0 += __shfl_xor_sync(0xffffffffu, Z0, 1);
    Z0 += __shfl_xor_sync(0xffffffffu, Z0, 2);
    Z1 += __shfl_xor_sync(0xffffffffu, Z1, 1);
    Z1 += __shfl_xor_sync(0xffffffffu, Z1, 2);
    const int r = lane >> 2;
    if ((lane & 3) == 0) {
        mw[warp][r]     = m0;  mw[warp][r + 8] = m1;
        zw[warp][r]     = Z0;  zw[warp][r + 8] = Z1;
    }
    __syncthreads();
    if (t < L_) {
        float M = -1e30f;
#pragma unroll
        for (int w = 0; w < NWARP_; w++) M = fmaxf(M, mw[w][t]);
        Mg[t] = M;
        float Zt = 0.0f;
#pragma unroll
        for (int w = 0; w < NWARP_; w++)
            Zt += zw[w][t] * __expf(mw[w][t] - M);
        int o = (bh * NS_ + split) * L_ + t;
        m_part[o] = M;
        z_part[o] = Zt;
    }
    __syncthreads();
    {
        float g0 = __expf(m0 - Mg[r]);
        float g1 = __expf(m1 - Mg[r + 8]);
        float* cb = (float*)hsm8 + warp * (L_ * HD_);
        int cbase = (lane & 3) * 2;
#pragma unroll
        for (int nt = 0; nt < 8; nt++) {
            int col = nt * 8 + cbase;
            *(float2*)&cb[r * HD_ + col]       = make_float2(O[nt][0] * g0, O[nt][1] * g0);
            *(float2*)&cb[(r + 8) * HD_ + col] = make_float2(O[nt][2] * g1, O[nt][3] * g1);
        }
    }
    __syncthreads();
    {
        const float* call = (const float*)hsm8;
        size_t ob = (size_t)(bh * NS_ + split) * (L_ * HD_);
        for (int i = t; i < L_ * HD_; i += 256) {
            float s = 0.0f;
#pragma unroll
            for (int w = 0; w < NWARP_; w++) s += call[w * (L_ * HD_) + i];
            acc_part[ob + i] = s;
        }
    }
}

__global__ void hop_combine(
    const float* __restrict__ m_part, const float* __restrict__ z_part,
    const float* __restrict__ acc_part, float* __restrict__ qdst, int final_mode)
{
    __shared__ float F[NS_][L_];
    __shared__ float Zs[L_];

    const int bh = blockIdx.x;
    const int b = bh / H_, h = bh % H_;
    const int t = threadIdx.x;

    if (t < L_) {
        float mv[NS_];
        float M = 0.0f;   // softmax_1 clamp at 0
#pragma unroll
        for (int i = 0; i < NS_; i++) {
            mv[i] = m_part[(bh * NS_ + i) * L_ + t];
            M = fmaxf(M, mv[i]);
        }
        float Zt = __expf(-M);   // phantom logit 0
#pragma unroll
        for (int i = 0; i < NS_; i++) {
            float f = __expf(mv[i] - M);
            F[i][t] = f;
            Zt += z_part[(bh * NS_ + i) * L_ + t] * f;
        }
        Zs[t] = Zt;
    }
    __syncthreads();

    for (int idx = t; idx < L_ * HD_; idx += 256) {
        int l = idx >> 6, d = idx & 63;
        float sum = 0.0f;
#pragma unroll
        for (int i = 0; i < NS_; i++)
            sum += acc_part[(size_t)(bh * NS_ + i) * (L_ * HD_) + idx] * F[i][l];
        sum /= Zs[l];
        if (final_mode)
            qdst[((size_t)b * L_ + l) * C_ + h * HD_ + d] = sum;
        else
            qdst[bh * (L_ * HD_) + idx] = sum;
    }
}

// ---------------------------------------------------------------------------
// Launch
// ---------------------------------------------------------------------------
extern "C" void kernel_launch(void* const* d_in, const int* in_sizes, int n_in,
                              void* d_out, int out_size)
{
    const float* x     = (const float*)d_in[0];
    const float* query = (const float*)d_in[1];
    const float* Wq    = (const float*)d_in[2];
    const float* Wk    = (const float*)d_in[3];
    const float* Wv    = (const float*)d_in[4];
    const float* Wproj = (const float*)d_in[5];
    const float* bproj = (const float*)d_in[6];
    float* out = (float*)d_out;

    float *q0_scr, *qf_scr, *tmp_scr, *q_state, *m_part, *z_part, *acc_part;
    __half *xh, *xl, *wh;
    __nv_bfloat16 *khg, *klg;
    cudaGetSymbolAddress((void**)&q0_scr, g_q0_scr);
    cudaGetSymbolAddress((void**)&qf_scr, g_qf_scr);
    cudaGetSymbolAddress((void**)&tmp_scr, g_tmp_scr);
    cudaGetSymbolAddress((void**)&q_state, g_q_state);
    cudaGetSymbolAddress((void**)&m_part, g_m_part);
    cudaGetSymbolAddress((void**)&z_part, g_z_part);
    cudaGetSymbolAddress((void**)&acc_part, g_acc_part);
    cudaGetSymbolAddress((void**)&xh, g_xh16);
    cudaGetSymbolAddress((void**)&xl, g_xl16);
    cudaGetSymbolAddress((void**)&wh, g_wh16);
    cudaGetSymbolAddress((void**)&khg, g_kh);
    cudaGetSymbolAddress((void**)&klg, g_kl);

    static bool attr_set = false;
    if (!attr_set) {
        cudaFuncSetAttribute(k_gemm_mma, cudaFuncAttributeMaxDynamicSharedMemorySize,
                             GEMM_SMEM_REQ);
        cudaFuncSetAttribute(hop_partial, cudaFuncAttributeMaxDynamicSharedMemorySize,
                             HOP_SMEM_);
        attr_set = true;
    }

    // convert: x -> fp16 hi/lo pair; Wk -> fp16
    {
        int nch_x = (MROWS_ * C_) / 8;
        convert_split_fp16<<<(nch_x + 255) / 256, 256>>>(x, xh, xl, nch_x);
        int nch_w = (C_ * C_) / 8;
        convert_fp16<<<(nch_w + 255) / 256, 256>>>(Wk, wh, nch_w);
    }
    // q0 = query @ Wq^T
    small_gemm_nt<<<dim3(C_ / 64, 1), 256>>>(query, Wq, nullptr, q0_scr, L_, C_, C_);
    // k = x @ Wk^T via fp16 HMMA 2-term -> kh/kl bf16 head-major
    k_gemm_mma<<<dim3(C_ / 128, MROWS_ / 128), GT_, GEMM_SMEM_REQ>>>(xh, xl, wh, khg, klg);
    // 3-step Hopfield attention (HMMA flash, NS=8 splits)
    hop_init_q<<<BH_, 256>>>(q0_scr, q_state);
    for (int s = 0; s < STEPS_; s++) {
        hop_partial<<<dim3(NS_, BH_), 256, HOP_SMEM_>>>(
            q_state, khg, klg, m_part, z_part, acc_part);
        hop_combine<<<BH_, 256>>>(m_part, z_part, acc_part,
                                  (s == STEPS_ - 1) ? qf_scr : q_state,
                                  (s == STEPS_ - 1) ? 1 : 0);
    }
    // out projections
    small_gemm_nt<<<dim3(C_ / 64, (B_ * L_) / 16), 256>>>(
        qf_scr, Wv, nullptr, tmp_scr, B_ * L_, C_, C_);
    small_gemm_nt<<<dim3(C_ / 64, (B_ * L_) / 16), 256>>>(
        tmp_scr, Wproj, bproj, out, B_ * L_, C_, C_);
}

// round 11
// speedup vs baseline: 1.1005x; 1.1005x over previous
#include <cuda_runtime.h>
#include <cuda_bf16.h>
#include <cuda_fp16.h>
#include <cstdint>

// ---------------------------------------------------------------------------
// Shapes (fixed by the problem)
// ---------------------------------------------------------------------------
#define B_  16
#define N_  4096
#define C_  768
#define L_  16
#define H_  12
#define HD_ 64
#define STEPS_ 3
#define BH_ (B_ * H_)               // 192

#define MROWS_ (B_ * N_)            // 65536
#define KSEG_  2                    // xh*wh, xl*wh  (fp16 2-term)
#define BK_    64
#define CH_PER_SEG_ (C_ / BK_)      // 12
#define NCHUNK_TOT_ (KSEG_ * CH_PER_SEG_)  // 24

// Hopfield split
#define TN_ 128
#define NWARP_ 8
#define NS_ 8
#define NT_SPL_ (N_ / NS_ / TN_)    // 4 tiles per split

// ---------------------------------------------------------------------------
// Scratch (__device__ globals)
// k stored as SINGLE fp16, head-major [B, H, N, 64]
// ---------------------------------------------------------------------------
__device__ __align__(16) __half g_k16[(size_t)BH_ * N_ * HD_];
__device__ __align__(16) __half g_xh16[(size_t)MROWS_ * C_];
__device__ __align__(16) __half g_xl16[(size_t)MROWS_ * C_];
__device__ __align__(16) __half g_wh16[(size_t)C_ * C_];
__device__ float g_q0_scr[L_ * C_];
__device__ float g_qf_scr[B_ * L_ * C_];
__device__ float g_tmp_scr[B_ * L_ * C_];
__device__ __align__(16) float g_q_state[BH_ * L_ * HD_];
__device__ float g_m_part[BH_ * NS_ * L_];
__device__ float g_z_part[BH_ * NS_ * L_];
__device__ __align__(16) float g_acc_part[(size_t)BH_ * NS_ * L_ * HD_];

// ---------------------------------------------------------------------------
// helpers
// ---------------------------------------------------------------------------
__device__ __forceinline__ uint32_t smem_u32(const void* p) {
    uint32_t a;
    asm("{ .reg .u64 t; cvta.to.shared.u64 t, %1; cvt.u32.u64 %0, t; }" : "=r"(a) : "l"(p));
    return a;
}
__device__ __forceinline__ void cpa16(uint32_t dst, const void* src) {
    asm volatile("cp.async.cg.shared.global [%0], [%1], 16;" :: "r"(dst), "l"(src));
}
#define CP_COMMIT() asm volatile("cp.async.commit_group;" ::: "memory")
#define CP_WAIT1()  asm volatile("cp.async.wait_group 1;" ::: "memory")
#define CP_WAIT0()  asm volatile("cp.async.wait_group 0;" ::: "memory")

__device__ __forceinline__ void ldsm_x4(uint32_t* r, uint32_t addr) {
    asm volatile("ldmatrix.sync.aligned.m8n8.x4.shared.b16 {%0,%1,%2,%3}, [%4];"
                 : "=r"(r[0]), "=r"(r[1]), "=r"(r[2]), "=r"(r[3]) : "r"(addr));
}
__device__ __forceinline__ void ldsm_x4t(uint32_t* r, uint32_t addr) {
    asm volatile("ldmatrix.sync.aligned.m8n8.x4.trans.shared.b16 {%0,%1,%2,%3}, [%4];"
                 : "=r"(r[0]), "=r"(r[1]), "=r"(r[2]), "=r"(r[3]) : "r"(addr));
}
__device__ __forceinline__ void mma_fp16(float* d, const uint32_t* a, const uint32_t* b) {
    asm volatile(
        "mma.sync.aligned.m16n8k16.row.col.f32.f16.f16.f32 "
        "{%0,%1,%2,%3}, {%4,%5,%6,%7}, {%8,%9}, {%0,%1,%2,%3};"
        : "+f"(d[0]), "+f"(d[1]), "+f"(d[2]), "+f"(d[3])
        : "r"(a[0]), "r"(a[1]), "r"(a[2]), "r"(a[3]), "r"(b[0]), "r"(b[1]));
}
__device__ __forceinline__ void split2h(float a, float b, uint32_t* hi, uint32_t* lo) {
    __half ha = __float2half(a), hb = __float2half(b);
    __half la = __float2half(a - __half2float(ha));
    __half lb = __float2half(b - __half2float(hb));
    *hi = (uint32_t)__half_as_ushort(ha) | ((uint32_t)__half_as_ushort(hb) << 16);
    *lo = (uint32_t)__half_as_ushort(la) | ((uint32_t)__half_as_ushort(lb) << 16);
}
__device__ __forceinline__ uint32_t pack_h2(float a, float b) {
    __half ha = __float2half(a), hb = __float2half(b);
    return (uint32_t)__half_as_ushort(ha) | ((uint32_t)__half_as_ushort(hb) << 16);
}

// ---------------------------------------------------------------------------
// Kernel A1: split fp32 -> (hi, lo) fp16 pair (for x)
// ---------------------------------------------------------------------------
__global__ void __launch_bounds__(256) convert_split_fp16(
    const float* __restrict__ src, __half* __restrict__ hi,
    __half* __restrict__ lo, int nchunks)
{
    int idx = blockIdx.x * 256 + threadIdx.x;
    if (idx >= nchunks) return;
    size_t e = (size_t)idx * 8;

    const float4* p = (const float4*)(src + e);
    float4 a = p[0], b = p[1];
    float v[8] = {a.x, a.y, a.z, a.w, b.x, b.y, b.z, b.w};

    uint32_t hp[4], lp[4];
#pragma unroll
    for (int i = 0; i < 4; i++) split2h(v[2*i], v[2*i+1], &hp[i], &lp[i]);
    *(uint4*)(hi + e) = make_uint4(hp[0], hp[1], hp[2], hp[3]);
    *(uint4*)(lo + e) = make_uint4(lp[0], lp[1], lp[2], lp[3]);
}

// Kernel A2: fp32 -> fp16 (for W)
__global__ void __launch_bounds__(256) convert_fp16(
    const float* __restrict__ src, __half* __restrict__ dst, int nchunks)
{
    int idx = blockIdx.x * 256 + threadIdx.x;
    if (idx >= nchunks) return;
    size_t e = (size_t)idx * 8;
    const float4* p = (const float4*)(src + e);
    float4 a = p[0], b = p[1];
    float v[8] = {a.x, a.y, a.z, a.w, b.x, b.y, b.z, b.w};
    uint32_t o[4];
#pragma unroll
    for (int i = 0; i < 4; i++) o[i] = pack_h2(v[2*i], v[2*i+1]);
    *(uint4*)(dst + e) = make_uint4(o[0], o[1], o[2], o[3]);
}

// ---------------------------------------------------------------------------
// Kernel B: HMMA GEMM  k = X @ Wk^T  (K = 2*768, fp16 2-term)
// Epilogue emits single fp16 k, head-major [B, H, N, 64].
// ---------------------------------------------------------------------------
#define KTB_ 16384
#define STAGEB_ (2 * KTB_)
#define NSTG_ 3
#define GEMM_SMEM_REQ (NSTG_ * STAGEB_)  // 98304
#define GT_ 128

__device__ __forceinline__ void load_tile64(
    uint32_t aS, uint32_t bS, const char* Aseg, const char* Bseg,
    int mt, int nt, int kk, int tid)
{
#pragma unroll
    for (int i = 0; i < 8; i++) {
        int idx = tid + i * GT_;
        int row = idx >> 3, c = idx & 7;
        uint32_t sw = (uint32_t)((c ^ (row & 7)) * 16);
        cpa16(aS + row * 128 + sw,
              Aseg + ((size_t)(mt * 128 + row) * C_ + kk + c * 8) * 2);
    }
#pragma unroll
    for (int i = 0; i < 8; i++) {
        int idx = tid + i * GT_;
        int row = idx >> 3, c = idx & 7;
        uint32_t sw = (uint32_t)((c ^ (row & 7)) * 16);
        cpa16(bS + row * 128 + sw,
              Bseg + ((size_t)(nt * 128 + row) * C_ + kk + c * 8) * 2);
    }
}

struct Frag { uint32_t a[4][4]; uint32_t b[4][4]; };

__device__ __forceinline__ void load_frag(
    Frag& f, uint32_t aS, uint32_t bS, int h,
    int wm, int wn, int arow_l, int agrp_l, int brow_l, int bgrp_l)
{
#pragma unroll
    for (int mi = 0; mi < 4; mi++) {
        int row = wm * 64 + mi * 16 + arow_l;
        int g   = (2 * h + agrp_l) ^ (row & 7);
        ldsm_x4(f.a[mi], aS + row * 128 + g * 16);
    }
#pragma unroll
    for (int p = 0; p < 4; p++) {
        int row = wn * 64 + p * 16 + brow_l;
        int g   = (2 * h + bgrp_l) ^ (row & 7);
        ldsm_x4(f.b[p], bS + row * 128 + g * 16);
    }
}

__global__ void __launch_bounds__(GT_, 2) k_gemm_mma(
    const __half* __restrict__ xh, const __half* __restrict__ xl,
    const __half* __restrict__ wh, __half* __restrict__ kg)
{
    extern __shared__ char dsm[];
    const uint32_t sbase = smem_u32(dsm);

    const int tid  = threadIdx.x;
    const int lane = tid & 31;
    const int warp = tid >> 5;
    const int wm   = warp >> 1;
    const int wn   = warp & 1;
    const int nt   = blockIdx.x;
    const int mt   = blockIdx.y;

    const char* Asrc[KSEG_] = {(const char*)xh, (const char*)xl};
    const char* Bsrc[KSEG_] = {(const char*)wh, (const char*)wh};

    float acc[4][8][4];
#pragma unroll
    for (int mi = 0; mi < 4; mi++)
#pragma unroll
        for (int ni = 0; ni < 8; ni++)
#pragma unroll
            for (int i = 0; i < 4; i++) acc[mi][ni][i] = 0.0f;

#pragma unroll
    for (int s = 0; s < NSTG_ - 1; s++) {
        load_tile64(sbase + s * STAGEB_, sbase + s * STAGEB_ + KTB_,
                    Asrc[0], Bsrc[0], mt, nt, s * BK_, tid);
        CP_COMMIT();
    }

    const int arow_l = lane & 15;
    const int agrp_l = lane >> 4;
    const int brow_l = (lane & 7) + ((lane >> 4) & 1) * 8;
    const int bgrp_l = (lane >> 3) & 1;

    Frag fr[2];

    for (int kc = 0; kc < NCHUNK_TOT_; kc++) {
        CP_WAIT1();
        __syncthreads();

        int pf = kc + NSTG_ - 1;
        if (pf < NCHUNK_TOT_) {
            int seg = pf / CH_PER_SEG_;
            int kk  = (pf % CH_PER_SEG_) * BK_;
            int s   = pf % NSTG_;
            load_tile64(sbase + s * STAGEB_, sbase + s * STAGEB_ + KTB_,
                        Asrc[seg], Bsrc[seg], mt, nt, kk, tid);
        }
        CP_COMMIT();

        const uint32_t aS = sbase + (kc % NSTG_) * STAGEB_;
        const uint32_t bS = aS + KTB_;

        load_frag(fr[0], aS, bS, 0, wm, wn, arow_l, agrp_l, brow_l, bgrp_l);
#pragma unroll
        for (int h = 0; h < 4; h++) {
            if (h < 3)
                load_frag(fr[(h + 1) & 1], aS, bS, h + 1,
                          wm, wn, arow_l, agrp_l, brow_l, bgrp_l);
            const Frag& f = fr[h & 1];
#pragma unroll
            for (int mi = 0; mi < 4; mi++)
#pragma unroll
                for (int ni = 0; ni < 8; ni++)
                    mma_fp16(acc[mi][ni], f.a[mi], f.b[ni >> 1] + (ni & 1) * 2);
        }
    }

    // epilogue: single fp16, scatter head-major [B, H, N, 64]
#pragma unroll
    for (int mi = 0; mi < 4; mi++) {
#pragma unroll
        for (int ni = 0; ni < 8; ni++) {
            int r = mt * 128 + wm * 64 + mi * 16 + (lane >> 2);
            int c = nt * 128 + wn * 64 + ni * 8 + (lane & 3) * 2;
            int b = r >> 12, n = r & (N_ - 1);
            int hh = c >> 6, d = c & 63;
            size_t addr = (((size_t)b * H_ + hh) * N_ + n) * HD_ + d;
            *(uint32_t*)&kg[addr]            = pack_h2(acc[mi][ni][0], acc[mi][ni][1]);
            *(uint32_t*)&kg[addr + 8 * HD_]  = pack_h2(acc[mi][ni][2], acc[mi][ni][3]);
        }
    }
}

// ---------------------------------------------------------------------------
// Kernel 2: small GEMM  C[M,N] = A[M,K]*B[N,K]^T (+bias), BK=64
// ---------------------------------------------------------------------------
__global__ void __launch_bounds__(256) small_gemm_nt(
    const float* __restrict__ A, const float* __restrict__ Bm,
    const float* __restrict__ bias, float* __restrict__ C,
    int M, int N, int K)
{
    __shared__ float AsT[64][17];
    __shared__ float BsT[64][65];

    const int t  = threadIdx.x;
    const int n0 = blockIdx.x * 64;
    const int m0 = blockIdx.y * 16;
    const int r0 = t >> 6;
    const int c  = t & 63;

    float acc[4] = {0.f, 0.f, 0.f, 0.f};

    for (int k0 = 0; k0 < K; k0 += 64) {
        __syncthreads();
        { int mm = t >> 4, k4 = (t & 15) * 4;
          float4 v = *(const float4*)&A[(long)(m0 + mm) * K + k0 + k4];
          AsT[k4 + 0][mm] = v.x; AsT[k4 + 1][mm] = v.y;
          AsT[k4 + 2][mm] = v.z; AsT[k4 + 3][mm] = v.w; }
        {
#pragma unroll
            for (int i = 0; i < 4; i++) {
                int idx = t + i * 256;
                int nn = idx >> 4, k4 = (idx & 15) * 4;
                float4 v = *(const float4*)&Bm[(long)(n0 + nn) * K + k0 + k4];
                BsT[k4 + 0][nn] = v.x; BsT[k4 + 1][nn] = v.y;
                BsT[k4 + 2][nn] = v.z; BsT[k4 + 3][nn] = v.w;
            }
        }
        __syncthreads();
#pragma unroll
        for (int kk = 0; kk < 64; kk++) {
            float bb = BsT[kk][c];
            acc[0] = fmaf(AsT[kk][r0 +  0], bb, acc[0]);
            acc[1] = fmaf(AsT[kk][r0 +  4], bb, acc[1]);
            acc[2] = fmaf(AsT[kk][r0 +  8], bb, acc[2]);
            acc[3] = fmaf(AsT[kk][r0 + 12], bb, acc[3]);
        }
    }
    float bv = bias ? bias[n0 + c] : 0.0f;
#pragma unroll
    for (int i = 0; i < 4; i++)
        C[(long)(m0 + r0 + 4 * i) * N + n0 + c] = acc[i] + bv;
}

// ---------------------------------------------------------------------------
// Hopfield step: single-fp16 k, q/P kept as fp16 hi/lo splits (2-term each).
// ---------------------------------------------------------------------------
__global__ void hop_init_q(const float* __restrict__ q0, float* __restrict__ qst)
{
    int bh = blockIdx.x, h = bh % H_;
    for (int i = threadIdx.x; i < L_ * HD_; i += 256) {
        int l = i >> 6, d = i & 63;
        qst[bh * (L_ * HD_) + i] = q0[l * C_ + h * HD_ + d];
    }
}

#define KROW_ 144
#define KTILE_PAD_ (128 * KROW_)
#define HOP_SMEM_ (2 * KTILE_PAD_ + 2 * L_ * KROW_)   // 41472 (combine reuse needs 32KB <= this)

__global__ void __launch_bounds__(256, 2) hop_partial(
    const float* __restrict__ qst, const __half* __restrict__ kg,
    float* __restrict__ m_part, float* __restrict__ z_part,
    float* __restrict__ acc_part)
{
    extern __shared__ __align__(16) char hsm8[];
    __shared__ float mw[NWARP_][L_];
    __shared__ float zw[NWARP_][L_];
    __shared__ float Mg[L_];

    const int t     = threadIdx.x;
    const int warp  = t >> 5;
    const int lane  = t & 31;
    const int split = blockIdx.x;
    const int bh    = blockIdx.y;
    const uint32_t sb  = smem_u32(hsm8);
    const uint32_t K0  = sb;
    const uint32_t QHo = sb + 2 * KTILE_PAD_;
    const uint32_t QLo = QHo + L_ * KROW_;

    const char* ksrc = (const char*)(kg + ((size_t)bh * N_ + split * (N_ / NS_)) * HD_);

    // prefetch tile 0 (16KB into padded rows): 1024 x 16B by 256 threads
#pragma unroll
    for (int i = 0; i < 4; i++) {
        int idx = t + i * 256;
        int row = idx >> 3, c = idx & 7;
        cpa16(K0 + row * KROW_ + c * 16, ksrc + (size_t)idx * 16);
    }
    CP_COMMIT();

    // q: scale, split to fp16 hi/lo, park in padded smem
    {
        float4 v = ((const float4*)(qst + bh * (L_ * HD_)))[t];
        int e = t * 4, r = e >> 6, d = e & 63;
        uint32_t h01, l01, h23, l23;
        split2h(v.x * 0.125f, v.y * 0.125f, &h01, &l01);
        split2h(v.z * 0.125f, v.w * 0.125f, &h23, &l23);
        char* qh = hsm8 + 2 * KTILE_PAD_ + r * KROW_ + d * 2;
        char* ql = qh + L_ * KROW_;
        *(uint32_t*)qh = h01; *(uint32_t*)(qh + 4) = h23;
        *(uint32_t*)ql = l01; *(uint32_t*)(ql + 4) = l23;
    }
    __syncthreads();

    // hoist q fragments
    const uint32_t qa_off = (uint32_t)((lane & 15) * KROW_ + (lane >> 4) * 16);
    uint32_t qfh[4][4], qfl[4][4];
#pragma unroll
    for (int kc = 0; kc < 4; kc++) {
        ldsm_x4(qfh[kc], QHo + qa_off + kc * 32);
        ldsm_x4(qfl[kc], QLo + qa_off + kc * 32);
    }

    float S[2][4], O[8][4];
#pragma unroll
    for (int i = 0; i < 8; i++)
#pragma unroll
        for (int j = 0; j < 4; j++) O[i][j] = 0.0f;
    float m0 = -1e30f, m1 = -1e30f, Z0 = 0.0f, Z1 = 0.0f;

    const uint32_t kb_off = (uint32_t)((warp * 16 + ((lane >> 4) & 1) * 8 + (lane & 7)) * KROW_
                                       + ((lane >> 3) & 1) * 16);
    const uint32_t v_off  = (uint32_t)((warp * 16 + (lane & 15)) * KROW_ + (lane >> 4) * 16);

    for (int tile = 0; tile < NT_SPL_; tile++) {
        if (tile + 1 < NT_SPL_) {
            uint32_t kd = K0 + ((tile + 1) & 1) * KTILE_PAD_;
            const char* src = ksrc + (size_t)(tile + 1) * (TN_ * HD_ * 2);
#pragma unroll
            for (int i = 0; i < 4; i++) {
                int idx = t + i * 256;
                int row = idx >> 3, c = idx & 7;
                cpa16(kd + row * KROW_ + c * 16, src + (size_t)idx * 16);
            }
            CP_COMMIT();
            CP_WAIT1();
        } else {
            CP_WAIT0();
        }
        __syncthreads();

        const uint32_t kb = K0 + (tile & 1) * KTILE_PAD_;

        // ---- scores: S = qh*k + ql*k ----
#pragma unroll
        for (int nt = 0; nt < 2; nt++)
#pragma unroll
            for (int i = 0; i < 4; i++) S[nt][i] = 0.0f;
#pragma unroll
        for (int kc = 0; kc < 4; kc++) {
            uint32_t k4[4];
            ldsm_x4(k4, kb + kb_off + kc * 32);
            mma_fp16(S[0], qfh[kc], k4);
            mma_fp16(S[1], qfh[kc], k4 + 2);
            mma_fp16(S[0], qfl[kc], k4);
            mma_fp16(S[1], qfl[kc], k4 + 2);
        }

        // ---- online softmax ----
        float mx0 = fmaxf(fmaxf(S[0][0], S[0][1]), fmaxf(S[1][0], S[1][1]));
        float mx1 = fmaxf(fmaxf(S[0][2], S[0][3]), fmaxf(S[1][2], S[1][3]));
        mx0 = fmaxf(mx0, __shfl_xor_sync(0xffffffffu, mx0, 1));
        mx0 = fmaxf(mx0, __shfl_xor_sync(0xffffffffu, mx0, 2));
        mx1 = fmaxf(mx1, __shfl_xor_sync(0xffffffffu, mx1, 1));
        mx1 = fmaxf(mx1, __shfl_xor_sync(0xffffffffu, mx1, 2));
        float mn0 = fmaxf(m0, mx0), mn1 = fmaxf(m1, mx1);
        float f0 = __expf(m0 - mn0), f1 = __expf(m1 - mn1);
        Z0 *= f0; Z1 *= f1;
#pragma unroll
        for (int nt = 0; nt < 8; nt++) {
            O[nt][0] *= f0; O[nt][1] *= f0;
            O[nt][2] *= f1; O[nt][3] *= f1;
        }
        float P00 = __expf(S[0][0] - mn0), P01 = __expf(S[0][1] - mn0);
        float P02 = __expf(S[0][2] - mn1), P03 = __expf(S[0][3] - mn1);
        float P10 = __expf(S[1][0] - mn0), P11 = __expf(S[1][1] - mn0);
        float P12 = __expf(S[1][2] - mn1), P13 = __expf(S[1][3] - mn1);
        Z0 += P00 + P01 + P10 + P11;
        Z1 += P02 + P03 + P12 + P13;
        uint32_t ph[4], pl[4];
        split2h(P00, P01, &ph[0], &pl[0]);
        split2h(P02, P03, &ph[1], &pl[1]);
        split2h(P10, P11, &ph[2], &pl[2]);
        split2h(P12, P13, &ph[3], &pl[3]);
        m0 = mn0; m1 = mn1;

        // ---- AV: O += ph*v + pl*v ----
#pragma unroll
        for (int hp = 0; hp < 4; hp++) {
            uint32_t v4[4];
            ldsm_x4t(v4, kb + v_off + hp * 32);
            mma_fp16(O[2*hp],     ph, v4);
            mma_fp16(O[2*hp],     pl, v4);
            mma_fp16(O[2*hp + 1], ph, v4 + 2);
            mma_fp16(O[2*hp + 1], pl, v4 + 2);
        }
        __syncthreads();
    }

    // ---- block combine ----
    Z0 += __shfl_xor_sync(0xffffffffu, Z0, 1);
    Z0 += __shfl_xor_sync(0xffffffffu, Z0, 2);
    Z1 += __shfl_xor_sync(0xffffffffu, Z1, 1);
    Z1 += __shfl_xor_sync(0xffffffffu, Z1, 2);
    const int r = lane >> 2;
    if ((lane & 3) == 0) {
        mw[warp][r]     = m0;  mw[warp][r + 8] = m1;
        zw[warp][r]     = Z0;  zw[warp][r + 8] = Z1;
    }
    __syncthreads();
    if (t < L_) {
        float M = -1e30f;
#pragma unroll
        for (int w = 0; w < NWARP_; w++) M = fmaxf(M, mw[w][t]);
        Mg[t] = M;
        float Zt = 0.0f;
#pragma unroll
        for (int w = 0; w < NWARP_; w++)
            Zt += zw[w][t] * __expf(mw[w][t] - M);
        int o = (bh * NS_ + split) * L_ + t;
        m_part[o] = M;
        z_part[o] = Zt;
    }
    __syncthreads();
    {
        float g0 = __expf(m0 - Mg[r]);
        float g1 = __expf(m1 - Mg[r + 8]);
        float* cb = (float*)hsm8 + warp * (L_ * HD_);
        int cbase = (lane & 3) * 2;
#pragma unroll
        for (int nt = 0; nt < 8; nt++) {
            int col = nt * 8 + cbase;
            *(float2*)&cb[r * HD_ + col]       = make_float2(O[nt][0] * g0, O[nt][1] * g0);
            *(float2*)&cb[(r + 8) * HD_ + col] = make_float2(O[nt][2] * g1, O[nt][3] * g1);
        }
    }
    __syncthreads();
    {
        const float* call = (const float*)hsm8;
        size_t ob = (size_t)(bh * NS_ + split) * (L_ * HD_);
        for (int i = t; i < L_ * HD_; i += 256) {
            float s = 0.0f;
#pragma unroll
            for (int w = 0; w < NWARP_; w++) s += call[w * (L_ * HD_) + i];
            acc_part[ob + i] = s;
        }
    }
}

__global__ void hop_combine(
    const float* __restrict__ m_part, const float* __restrict__ z_part,
    const float* __restrict__ acc_part, float* __restrict__ qdst, int final_mode)
{
    __shared__ float F[NS_][L_];
    __shared__ float Zs[L_];

    const int bh = blockIdx.x;
    const int b = bh / H_, h = bh % H_;
    const int t = threadIdx.x;

    if (t < L_) {
        float mv[NS_];
        float M = 0.0f;   // softmax_1 clamp at 0
#pragma unroll
        for (int i = 0; i < NS_; i++) {
            mv[i] = m_part[(bh * NS_ + i) * L_ + t];
            M = fmaxf(M, mv[i]);
        }
        float Zt = __expf(-M);   // phantom logit 0
#pragma unroll
        for (int i = 0; i < NS_; i++) {
            float f = __expf(mv[i] - M);
            F[i][t] = f;
            Zt += z_part[(bh * NS_ + i) * L_ + t] * f;
        }
        Zs[t] = Zt;
    }
    __syncthreads();

    for (int idx = t; idx < L_ * HD_; idx += 256) {
        int l = idx >> 6, d = idx & 63;
        float sum = 0.0f;
#pragma unroll
        for (int i = 0; i < NS_; i++)
            sum += acc_part[(size_t)(bh * NS_ + i) * (L_ * HD_) + idx] * F[i][l];
        sum /= Zs[l];
        if (final_mode)
            qdst[((size_t)b * L_ + l) * C_ + h * HD_ + d] = sum;
        else
            qdst[bh * (L_ * HD_) + idx] = sum;
    }
}

// ---------------------------------------------------------------------------
// Launch
// ---------------------------------------------------------------------------
extern "C" void kernel_launch(void* const* d_in, const int* in_sizes, int n_in,
                              void* d_out, int out_size)
{
    const float* x     = (const float*)d_in[0];
    const float* query = (const float*)d_in[1];
    const float* Wq    = (const float*)d_in[2];
    const float* Wk    = (const float*)d_in[3];
    const float* Wv    = (const float*)d_in[4];
    const float* Wproj = (const float*)d_in[5];
    const float* bproj = (const float*)d_in[6];
    float* out = (float*)d_out;

    float *q0_scr, *qf_scr, *tmp_scr, *q_state, *m_part, *z_part, *acc_part;
    __half *xh, *xl, *wh, *kg;
    cudaGetSymbolAddress((void**)&q0_scr, g_q0_scr);
    cudaGetSymbolAddress((void**)&qf_scr, g_qf_scr);
    cudaGetSymbolAddress((void**)&tmp_scr, g_tmp_scr);
    cudaGetSymbolAddress((void**)&q_state, g_q_state);
    cudaGetSymbolAddress((void**)&m_part, g_m_part);
    cudaGetSymbolAddress((void**)&z_part, g_z_part);
    cudaGetSymbolAddress((void**)&acc_part, g_acc_part);
    cudaGetSymbolAddress((void**)&xh, g_xh16);
    cudaGetSymbolAddress((void**)&xl, g_xl16);
    cudaGetSymbolAddress((void**)&wh, g_wh16);
    cudaGetSymbolAddress((void**)&kg, g_k16);

    static bool attr_set = false;
    if (!attr_set) {
        cudaFuncSetAttribute(k_gemm_mma, cudaFuncAttributeMaxDynamicSharedMemorySize,
                             GEMM_SMEM_REQ);
        cudaFuncSetAttribute(hop_partial, cudaFuncAttributeMaxDynamicSharedMemorySize,
                             HOP_SMEM_);
        attr_set = true;
    }

    // convert: x -> fp16 hi/lo pair; Wk -> fp16
    {
        int nch_x = (MROWS_ * C_) / 8;
        convert_split_fp16<<<(nch_x + 255) / 256, 256>>>(x, xh, xl, nch_x);
        int nch_w = (C_ * C_) / 8;
        convert_fp16<<<(nch_w + 255) / 256, 256>>>(Wk, wh, nch_w);
    }
    // q0 = query @ Wq^T
    small_gemm_nt<<<dim3(C_ / 64, 1), 256>>>(query, Wq, nullptr, q0_scr, L_, C_, C_);
    // k = x @ Wk^T via fp16 HMMA 2-term -> fp16 head-major
    k_gemm_mma<<<dim3(C_ / 128, MROWS_ / 128), GT_, GEMM_SMEM_REQ>>>(xh, xl, wh, kg);
    // 3-step Hopfield attention (HMMA flash, NS=8 splits)
    hop_init_q<<<BH_, 256>>>(q0_scr, q_state);
    for (int s = 0; s < STEPS_; s++) {
        hop_partial<<<dim3(NS_, BH_), 256, HOP_SMEM_>>>(
            q_state, kg, m_part, z_part, acc_part);
        hop_combine<<<BH_, 256>>>(m_part, z_part, acc_part,
                                  (s == STEPS_ - 1) ? qf_scr : q_state,
                                  (s == STEPS_ - 1) ? 1 : 0);
    }
    // out projections
    small_gemm_nt<<<dim3(C_ / 64, (B_ * L_) / 16), 256>>>(
        qf_scr, Wv, nullptr, tmp_scr, B_ * L_, C_, C_);
    small_gemm_nt<<<dim3(C_ / 64, (B_ * L_) / 16), 256>>>(
        tmp_scr, Wproj, bproj, out, B_ * L_, C_, C_);
}

// round 12
// speedup vs baseline: 1.5041x; 1.3668x over previous
#include <cuda_runtime.h>
#include <cuda_bf16.h>
#include <cuda_fp16.h>
#include <cstdint>

// ---------------------------------------------------------------------------
// Shapes (fixed by the problem)
// ---------------------------------------------------------------------------
#define B_  16
#define N_  4096
#define C_  768
#define L_  16
#define H_  12
#define HD_ 64
#define STEPS_ 3
#define BH_ (B_ * H_)               // 192

#define MROWS_ (B_ * N_)            // 65536
#define BK_    64
#define NCHUNK_TOT_ (C_ / BK_)      // 12 (single fp16 term)

// Hopfield split
#define TN_ 128
#define NWARP_ 8
#define NS_ 8
#define NT_SPL_ (N_ / NS_ / TN_)    // 4 tiles per split

// ---------------------------------------------------------------------------
// Scratch (__device__ globals)
// k stored as SINGLE fp16, head-major [B, H, N, 64]
// ---------------------------------------------------------------------------
__device__ __align__(16) __half g_k16[(size_t)BH_ * N_ * HD_];
__device__ __align__(16) __half g_x16[(size_t)MROWS_ * C_];
__device__ __align__(16) __half g_w16[(size_t)C_ * C_];
__device__ float g_q0_scr[L_ * C_];
__device__ float g_qf_scr[B_ * L_ * C_];
__device__ float g_tmp_scr[B_ * L_ * C_];
__device__ __align__(16) float g_q_state[BH_ * L_ * HD_];
__device__ float g_m_part[BH_ * NS_ * L_];
__device__ float g_z_part[BH_ * NS_ * L_];
__device__ __align__(16) float g_acc_part[(size_t)BH_ * NS_ * L_ * HD_];

// ---------------------------------------------------------------------------
// helpers
// ---------------------------------------------------------------------------
__device__ __forceinline__ uint32_t smem_u32(const void* p) {
    uint32_t a;
    asm("{ .reg .u64 t; cvta.to.shared.u64 t, %1; cvt.u32.u64 %0, t; }" : "=r"(a) : "l"(p));
    return a;
}
__device__ __forceinline__ void cpa16(uint32_t dst, const void* src) {
    asm volatile("cp.async.cg.shared.global [%0], [%1], 16;" :: "r"(dst), "l"(src));
}
#define CP_COMMIT() asm volatile("cp.async.commit_group;" ::: "memory")
#define CP_WAIT1()  asm volatile("cp.async.wait_group 1;" ::: "memory")
#define CP_WAIT0()  asm volatile("cp.async.wait_group 0;" ::: "memory")

__device__ __forceinline__ void ldsm_x4(uint32_t* r, uint32_t addr) {
    asm volatile("ldmatrix.sync.aligned.m8n8.x4.shared.b16 {%0,%1,%2,%3}, [%4];"
                 : "=r"(r[0]), "=r"(r[1]), "=r"(r[2]), "=r"(r[3]) : "r"(addr));
}
__device__ __forceinline__ void ldsm_x4t(uint32_t* r, uint32_t addr) {
    asm volatile("ldmatrix.sync.aligned.m8n8.x4.trans.shared.b16 {%0,%1,%2,%3}, [%4];"
                 : "=r"(r[0]), "=r"(r[1]), "=r"(r[2]), "=r"(r[3]) : "r"(addr));
}
__device__ __forceinline__ void mma_fp16(float* d, const uint32_t* a, const uint32_t* b) {
    asm volatile(
        "mma.sync.aligned.m16n8k16.row.col.f32.f16.f16.f32 "
        "{%0,%1,%2,%3}, {%4,%5,%6,%7}, {%8,%9}, {%0,%1,%2,%3};"
        : "+f"(d[0]), "+f"(d[1]), "+f"(d[2]), "+f"(d[3])
        : "r"(a[0]), "r"(a[1]), "r"(a[2]), "r"(a[3]), "r"(b[0]), "r"(b[1]));
}
__device__ __forceinline__ void split2h(float a, float b, uint32_t* hi, uint32_t* lo) {
    __half ha = __float2half(a), hb = __float2half(b);
    __half la = __float2half(a - __half2float(ha));
    __half lb = __float2half(b - __half2float(hb));
    *hi = (uint32_t)__half_as_ushort(ha) | ((uint32_t)__half_as_ushort(hb) << 16);
    *lo = (uint32_t)__half_as_ushort(la) | ((uint32_t)__half_as_ushort(lb) << 16);
}
__device__ __forceinline__ uint32_t pack_h2(float a, float b) {
    __half ha = __float2half(a), hb = __float2half(b);
    return (uint32_t)__half_as_ushort(ha) | ((uint32_t)__half_as_ushort(hb) << 16);
}

// ---------------------------------------------------------------------------
// Kernel A: fp32 -> fp16
// ---------------------------------------------------------------------------
__global__ void __launch_bounds__(256) convert_fp16(
    const float* __restrict__ src, __half* __restrict__ dst, int nchunks)
{
    int idx = blockIdx.x * 256 + threadIdx.x;
    if (idx >= nchunks) return;
    size_t e = (size_t)idx * 8;
    const float4* p = (const float4*)(src + e);
    float4 a = p[0], b = p[1];
    float v[8] = {a.x, a.y, a.z, a.w, b.x, b.y, b.z, b.w};
    uint32_t o[4];
#pragma unroll
    for (int i = 0; i < 4; i++) o[i] = pack_h2(v[2*i], v[2*i+1]);
    *(uint4*)(dst + e) = make_uint4(o[0], o[1], o[2], o[3]);
}

// ---------------------------------------------------------------------------
// Kernel B: HMMA GEMM  k = fp16(x) @ fp16(Wk)^T  (K = 768, single term)
// CTA 128x128, 4 warps of 64x64, BK=64, 3-stage cp.async, XOR swizzle,
// 2 CTAs/SM, fragment double-buffering. Emits fp16 k head-major [B,H,N,64].
// ---------------------------------------------------------------------------
#define KTB_ 16384
#define STAGEB_ (2 * KTB_)
#define NSTG_ 3
#define GEMM_SMEM_REQ (NSTG_ * STAGEB_)  // 98304
#define GT_ 128

__device__ __forceinline__ void load_tile64(
    uint32_t aS, uint32_t bS, const char* Aseg, const char* Bseg,
    int mt, int nt, int kk, int tid)
{
#pragma unroll
    for (int i = 0; i < 8; i++) {
        int idx = tid + i * GT_;
        int row = idx >> 3, c = idx & 7;
        uint32_t sw = (uint32_t)((c ^ (row & 7)) * 16);
        cpa16(aS + row * 128 + sw,
              Aseg + ((size_t)(mt * 128 + row) * C_ + kk + c * 8) * 2);
    }
#pragma unroll
    for (int i = 0; i < 8; i++) {
        int idx = tid + i * GT_;
        int row = idx >> 3, c = idx & 7;
        uint32_t sw = (uint32_t)((c ^ (row & 7)) * 16);
        cpa16(bS + row * 128 + sw,
              Bseg + ((size_t)(nt * 128 + row) * C_ + kk + c * 8) * 2);
    }
}

struct Frag { uint32_t a[4][4]; uint32_t b[4][4]; };

__device__ __forceinline__ void load_frag(
    Frag& f, uint32_t aS, uint32_t bS, int h,
    int wm, int wn, int arow_l, int agrp_l, int brow_l, int bgrp_l)
{
#pragma unroll
    for (int mi = 0; mi < 4; mi++) {
        int row = wm * 64 + mi * 16 + arow_l;
        int g   = (2 * h + agrp_l) ^ (row & 7);
        ldsm_x4(f.a[mi], aS + row * 128 + g * 16);
    }
#pragma unroll
    for (int p = 0; p < 4; p++) {
        int row = wn * 64 + p * 16 + brow_l;
        int g   = (2 * h + bgrp_l) ^ (row & 7);
        ldsm_x4(f.b[p], bS + row * 128 + g * 16);
    }
}

__global__ void __launch_bounds__(GT_, 2) k_gemm_mma(
    const __half* __restrict__ xg, const __half* __restrict__ wg,
    __half* __restrict__ kg)
{
    extern __shared__ char dsm[];
    const uint32_t sbase = smem_u32(dsm);

    const int tid  = threadIdx.x;
    const int lane = tid & 31;
    const int warp = tid >> 5;
    const int wm   = warp >> 1;
    const int wn   = warp & 1;
    const int nt   = blockIdx.x;
    const int mt   = blockIdx.y;

    float acc[4][8][4];
#pragma unroll
    for (int mi = 0; mi < 4; mi++)
#pragma unroll
        for (int ni = 0; ni < 8; ni++)
#pragma unroll
            for (int i = 0; i < 4; i++) acc[mi][ni][i] = 0.0f;

#pragma unroll
    for (int s = 0; s < NSTG_ - 1; s++) {
        load_tile64(sbase + s * STAGEB_, sbase + s * STAGEB_ + KTB_,
                    (const char*)xg, (const char*)wg, mt, nt, s * BK_, tid);
        CP_COMMIT();
    }

    const int arow_l = lane & 15;
    const int agrp_l = lane >> 4;
    const int brow_l = (lane & 7) + ((lane >> 4) & 1) * 8;
    const int bgrp_l = (lane >> 3) & 1;

    Frag fr[2];

    for (int kc = 0; kc < NCHUNK_TOT_; kc++) {
        CP_WAIT1();
        __syncthreads();

        int pf = kc + NSTG_ - 1;
        if (pf < NCHUNK_TOT_) {
            int s = pf % NSTG_;
            load_tile64(sbase + s * STAGEB_, sbase + s * STAGEB_ + KTB_,
                        (const char*)xg, (const char*)wg, mt, nt, pf * BK_, tid);
        }
        CP_COMMIT();

        const uint32_t aS = sbase + (kc % NSTG_) * STAGEB_;
        const uint32_t bS = aS + KTB_;

        load_frag(fr[0], aS, bS, 0, wm, wn, arow_l, agrp_l, brow_l, bgrp_l);
#pragma unroll
        for (int h = 0; h < 4; h++) {
            if (h < 3)
                load_frag(fr[(h + 1) & 1], aS, bS, h + 1,
                          wm, wn, arow_l, agrp_l, brow_l, bgrp_l);
            const Frag& f = fr[h & 1];
#pragma unroll
            for (int mi = 0; mi < 4; mi++)
#pragma unroll
                for (int ni = 0; ni < 8; ni++)
                    mma_fp16(acc[mi][ni], f.a[mi], f.b[ni >> 1] + (ni & 1) * 2);
        }
    }

    // epilogue: fp16 k, scatter head-major [B, H, N, 64]
#pragma unroll
    for (int mi = 0; mi < 4; mi++) {
#pragma unroll
        for (int ni = 0; ni < 8; ni++) {
            int r = mt * 128 + wm * 64 + mi * 16 + (lane >> 2);
            int c = nt * 128 + wn * 64 + ni * 8 + (lane & 3) * 2;
            int b = r >> 12, n = r & (N_ - 1);
            int hh = c >> 6, d = c & 63;
            size_t addr = (((size_t)b * H_ + hh) * N_ + n) * HD_ + d;
            *(uint32_t*)&kg[addr]            = pack_h2(acc[mi][ni][0], acc[mi][ni][1]);
            *(uint32_t*)&kg[addr + 8 * HD_]  = pack_h2(acc[mi][ni][2], acc[mi][ni][3]);
        }
    }
}

// ---------------------------------------------------------------------------
// Kernel 2: small GEMM  C[M,N] = A[M,K]*B[N,K]^T (+bias), BK=64
// ---------------------------------------------------------------------------
__global__ void __launch_bounds__(256) small_gemm_nt(
    const float* __restrict__ A, const float* __restrict__ Bm,
    const float* __restrict__ bias, float* __restrict__ C,
    int M, int N, int K)
{
    __shared__ float AsT[64][17];
    __shared__ float BsT[64][65];

    const int t  = threadIdx.x;
    const int n0 = blockIdx.x * 64;
    const int m0 = blockIdx.y * 16;
    const int r0 = t >> 6;
    const int c  = t & 63;

    float acc[4] = {0.f, 0.f, 0.f, 0.f};

    for (int k0 = 0; k0 < K; k0 += 64) {
        __syncthreads();
        { int mm = t >> 4, k4 = (t & 15) * 4;
          float4 v = *(const float4*)&A[(long)(m0 + mm) * K + k0 + k4];
          AsT[k4 + 0][mm] = v.x; AsT[k4 + 1][mm] = v.y;
          AsT[k4 + 2][mm] = v.z; AsT[k4 + 3][mm] = v.w; }
        {
#pragma unroll
            for (int i = 0; i < 4; i++) {
                int idx = t + i * 256;
                int nn = idx >> 4, k4 = (idx & 15) * 4;
                float4 v = *(const float4*)&Bm[(long)(n0 + nn) * K + k0 + k4];
                BsT[k4 + 0][nn] = v.x; BsT[k4 + 1][nn] = v.y;
                BsT[k4 + 2][nn] = v.z; BsT[k4 + 3][nn] = v.w;
            }
        }
        __syncthreads();
#pragma unroll
        for (int kk = 0; kk < 64; kk++) {
            float bb = BsT[kk][c];
            acc[0] = fmaf(AsT[kk][r0 +  0], bb, acc[0]);
            acc[1] = fmaf(AsT[kk][r0 +  4], bb, acc[1]);
            acc[2] = fmaf(AsT[kk][r0 +  8], bb, acc[2]);
            acc[3] = fmaf(AsT[kk][r0 + 12], bb, acc[3]);
        }
    }
    float bv = bias ? bias[n0 + c] : 0.0f;
#pragma unroll
    for (int i = 0; i < 4; i++)
        C[(long)(m0 + r0 + 4 * i) * N + n0 + c] = acc[i] + bv;
}

// ---------------------------------------------------------------------------
// Hopfield step: single-fp16 k, q/P as fp16 hi/lo splits (2-term each).
// ---------------------------------------------------------------------------
__global__ void hop_init_q(const float* __restrict__ q0, float* __restrict__ qst)
{
    int bh = blockIdx.x, h = bh % H_;
    for (int i = threadIdx.x; i < L_ * HD_; i += 256) {
        int l = i >> 6, d = i & 63;
        qst[bh * (L_ * HD_) + i] = q0[l * C_ + h * HD_ + d];
    }
}

#define KROW_ 144
#define KTILE_PAD_ (128 * KROW_)
#define HOP_SMEM_ (2 * KTILE_PAD_ + 2 * L_ * KROW_)   // 41472

__global__ void __launch_bounds__(256, 2) hop_partial(
    const float* __restrict__ qst, const __half* __restrict__ kg,
    float* __restrict__ m_part, float* __restrict__ z_part,
    float* __restrict__ acc_part)
{
    extern __shared__ __align__(16) char hsm8[];
    __shared__ float mw[NWARP_][L_];
    __shared__ float zw[NWARP_][L_];
    __shared__ float Mg[L_];

    const int t     = threadIdx.x;
    const int warp  = t >> 5;
    const int lane  = t & 31;
    const int split = blockIdx.x;
    const int bh    = blockIdx.y;
    const uint32_t sb  = smem_u32(hsm8);
    const uint32_t K0  = sb;
    const uint32_t QHo = sb + 2 * KTILE_PAD_;
    const uint32_t QLo = QHo + L_ * KROW_;

    const char* ksrc = (const char*)(kg + ((size_t)bh * N_ + split * (N_ / NS_)) * HD_);

    // prefetch tile 0
#pragma unroll
    for (int i = 0; i < 4; i++) {
        int idx = t + i * 256;
        int row = idx >> 3, c = idx & 7;
        cpa16(K0 + row * KROW_ + c * 16, ksrc + (size_t)idx * 16);
    }
    CP_COMMIT();

    // q: scale, split to fp16 hi/lo, park in padded smem
    {
        float4 v = ((const float4*)(qst + bh * (L_ * HD_)))[t];
        int e = t * 4, r = e >> 6, d = e & 63;
        uint32_t h01, l01, h23, l23;
        split2h(v.x * 0.125f, v.y * 0.125f, &h01, &l01);
        split2h(v.z * 0.125f, v.w * 0.125f, &h23, &l23);
        char* qh = hsm8 + 2 * KTILE_PAD_ + r * KROW_ + d * 2;
        char* ql = qh + L_ * KROW_;
        *(uint32_t*)qh = h01; *(uint32_t*)(qh + 4) = h23;
        *(uint32_t*)ql = l01; *(uint32_t*)(ql + 4) = l23;
    }
    __syncthreads();

    // hoist q fragments
    const uint32_t qa_off = (uint32_t)((lane & 15) * KROW_ + (lane >> 4) * 16);
    uint32_t qfh[4][4], qfl[4][4];
#pragma unroll
    for (int kc = 0; kc < 4; kc++) {
        ldsm_x4(qfh[kc], QHo + qa_off + kc * 32);
        ldsm_x4(qfl[kc], QLo + qa_off + kc * 32);
    }

    float S[2][4], O[8][4];
#pragma unroll
    for (int i = 0; i < 8; i++)
#pragma unroll
        for (int j = 0; j < 4; j++) O[i][j] = 0.0f;
    float m0 = -1e30f, m1 = -1e30f, Z0 = 0.0f, Z1 = 0.0f;

    const uint32_t kb_off = (uint32_t)((warp * 16 + ((lane >> 4) & 1) * 8 + (lane & 7)) * KROW_
                                       + ((lane >> 3) & 1) * 16);
    const uint32_t v_off  = (uint32_t)((warp * 16 + (lane & 15)) * KROW_ + (lane >> 4) * 16);

    for (int tile = 0; tile < NT_SPL_; tile++) {
        if (tile + 1 < NT_SPL_) {
            uint32_t kd = K0 + ((tile + 1) & 1) * KTILE_PAD_;
            const char* src = ksrc + (size_t)(tile + 1) * (TN_ * HD_ * 2);
#pragma unroll
            for (int i = 0; i < 4; i++) {
                int idx = t + i * 256;
                int row = idx >> 3, c = idx & 7;
                cpa16(kd + row * KROW_ + c * 16, src + (size_t)idx * 16);
            }
            CP_COMMIT();
            CP_WAIT1();
        } else {
            CP_WAIT0();
        }
        __syncthreads();

        const uint32_t kb = K0 + (tile & 1) * KTILE_PAD_;

        // ---- scores: S = qh*k + ql*k ----
#pragma unroll
        for (int nt = 0; nt < 2; nt++)
#pragma unroll
            for (int i = 0; i < 4; i++) S[nt][i] = 0.0f;
#pragma unroll
        for (int kc = 0; kc < 4; kc++) {
            uint32_t k4[4];
            ldsm_x4(k4, kb + kb_off + kc * 32);
            mma_fp16(S[0], qfh[kc], k4);
            mma_fp16(S[1], qfh[kc], k4 + 2);
            mma_fp16(S[0], qfl[kc], k4);
            mma_fp16(S[1], qfl[kc], k4 + 2);
        }

        // ---- online softmax ----
        float mx0 = fmaxf(fmaxf(S[0][0], S[0][1]), fmaxf(S[1][0], S[1][1]));
        float mx1 = fmaxf(fmaxf(S[0][2], S[0][3]), fmaxf(S[1][2], S[1][3]));
        mx0 = fmaxf(mx0, __shfl_xor_sync(0xffffffffu, mx0, 1));
        mx0 = fmaxf(mx0, __shfl_xor_sync(0xffffffffu, mx0, 2));
        mx1 = fmaxf(mx1, __shfl_xor_sync(0xffffffffu, mx1, 1));
        mx1 = fmaxf(mx1, __shfl_xor_sync(0xffffffffu, mx1, 2));
        float mn0 = fmaxf(m0, mx0), mn1 = fmaxf(m1, mx1);
        float f0 = __expf(m0 - mn0), f1 = __expf(m1 - mn1);
        Z0 *= f0; Z1 *= f1;
#pragma unroll
        for (int nt = 0; nt < 8; nt++) {
            O[nt][0] *= f0; O[nt][1] *= f0;
            O[nt][2] *= f1; O[nt][3] *= f1;
        }
        float P00 = __expf(S[0][0] - mn0), P01 = __expf(S[0][1] - mn0);
        float P02 = __expf(S[0][2] - mn1), P03 = __expf(S[0][3] - mn1);
        float P10 = __expf(S[1][0] - mn0), P11 = __expf(S[1][1] - mn0);
        float P12 = __expf(S[1][2] - mn1), P13 = __expf(S[1][3] - mn1);
        Z0 += P00 + P01 + P10 + P11;
        Z1 += P02 + P03 + P12 + P13;
        uint32_t ph[4], pl[4];
        split2h(P00, P01, &ph[0], &pl[0]);
        split2h(P02, P03, &ph[1], &pl[1]);
        split2h(P10, P11, &ph[2], &pl[2]);
        split2h(P12, P13, &ph[3], &pl[3]);
        m0 = mn0; m1 = mn1;

        // ---- AV: O += ph*v + pl*v ----
#pragma unroll
        for (int hp = 0; hp < 4; hp++) {
            uint32_t v4[4];
            ldsm_x4t(v4, kb + v_off + hp * 32);
            mma_fp16(O[2*hp],     ph, v4);
            mma_fp16(O[2*hp],     pl, v4);
            mma_fp16(O[2*hp + 1], ph, v4 + 2);
            mma_fp16(O[2*hp + 1], pl, v4 + 2);
        }
        __syncthreads();
    }

    // ---- block combine ----
    Z0 += __shfl_xor_sync(0xffffffffu, Z0, 1);
    Z0 += __shfl_xor_sync(0xffffffffu, Z0, 2);
    Z1 += __shfl_xor_sync(0xffffffffu, Z1, 1);
    Z1 += __shfl_xor_sync(0xffffffffu, Z1, 2);
    const int r = lane >> 2;
    if ((lane & 3) == 0) {
        mw[warp][r]     = m0;  mw[warp][r + 8] = m1;
        zw[warp][r]     = Z0;  zw[warp][r + 8] = Z1;
    }
    __syncthreads();
    if (t < L_) {
        float M = -1e30f;
#pragma unroll
        for (int w = 0; w < NWARP_; w++) M = fmaxf(M, mw[w][t]);
        Mg[t] = M;
        float Zt = 0.0f;
#pragma unroll
        for (int w = 0; w < NWARP_; w++)
            Zt += zw[w][t] * __expf(mw[w][t] - M);
        int o = (bh * NS_ + split) * L_ + t;
        m_part[o] = M;
        z_part[o] = Zt;
    }
    __syncthreads();
    {
        float g0 = __expf(m0 - Mg[r]);
        float g1 = __expf(m1 - Mg[r + 8]);
        float* cb = (float*)hsm8 + warp * (L_ * HD_);
        int cbase = (lane & 3) * 2;
#pragma unroll
        for (int nt = 0; nt < 8; nt++) {
            int col = nt * 8 + cbase;
            *(float2*)&cb[r * HD_ + col]       = make_float2(O[nt][0] * g0, O[nt][1] * g0);
            *(float2*)&cb[(r + 8) * HD_ + col] = make_float2(O[nt][2] * g1, O[nt][3] * g1);
        }
    }
    __syncthreads();
    {
        const float* call = (const float*)hsm8;
        size_t ob = (size_t)(bh * NS_ + split) * (L_ * HD_);
        for (int i = t; i < L_ * HD_; i += 256) {
            float s = 0.0f;
#pragma unroll
            for (int w = 0; w < NWARP_; w++) s += call[w * (L_ * HD_) + i];
            acc_part[ob + i] = s;
        }
    }
}

__global__ void hop_combine(
    const float* __restrict__ m_part, const float* __restrict__ z_part,
    const float* __restrict__ acc_part, float* __restrict__ qdst, int final_mode)
{
    __shared__ float F[NS_][L_];
    __shared__ float Zs[L_];

    const int bh = blockIdx.x;
    const int b = bh / H_, h = bh % H_;
    const int t = threadIdx.x;

    if (t < L_) {
        float mv[NS_];
        float M = 0.0f;   // softmax_1 clamp at 0
#pragma unroll
        for (int i = 0; i < NS_; i++) {
            mv[i] = m_part[(bh * NS_ + i) * L_ + t];
            M = fmaxf(M, mv[i]);
        }
        float Zt = __expf(-M);   // phantom logit 0
#pragma unroll
        for (int i = 0; i < NS_; i++) {
            float f = __expf(mv[i] - M);
            F[i][t] = f;
            Zt += z_part[(bh * NS_ + i) * L_ + t] * f;
        }
        Zs[t] = Zt;
    }
    __syncthreads();

    for (int idx = t; idx < L_ * HD_; idx += 256) {
        int l = idx >> 6, d = idx & 63;
        float sum = 0.0f;
#pragma unroll
        for (int i = 0; i < NS_; i++)
            sum += acc_part[(size_t)(bh * NS_ + i) * (L_ * HD_) + idx] * F[i][l];
        sum /= Zs[l];
        if (final_mode)
            qdst[((size_t)b * L_ + l) * C_ + h * HD_ + d] = sum;
        else
            qdst[bh * (L_ * HD_) + idx] = sum;
    }
}

// ---------------------------------------------------------------------------
// Launch
// ---------------------------------------------------------------------------
extern "C" void kernel_launch(void* const* d_in, const int* in_sizes, int n_in,
                              void* d_out, int out_size)
{
    const float* x     = (const float*)d_in[0];
    const float* query = (const float*)d_in[1];
    const float* Wq    = (const float*)d_in[2];
    const float* Wk    = (const float*)d_in[3];
    const float* Wv    = (const float*)d_in[4];
    const float* Wproj = (const float*)d_in[5];
    const float* bproj = (const float*)d_in[6];
    float* out = (float*)d_out;

    float *q0_scr, *qf_scr, *tmp_scr, *q_state, *m_part, *z_part, *acc_part;
    __half *xg, *wg, *kg;
    cudaGetSymbolAddress((void**)&q0_scr, g_q0_scr);
    cudaGetSymbolAddress((void**)&qf_scr, g_qf_scr);
    cudaGetSymbolAddress((void**)&tmp_scr, g_tmp_scr);
    cudaGetSymbolAddress((void**)&q_state, g_q_state);
    cudaGetSymbolAddress((void**)&m_part, g_m_part);
    cudaGetSymbolAddress((void**)&z_part, g_z_part);
    cudaGetSymbolAddress((void**)&acc_part, g_acc_part);
    cudaGetSymbolAddress((void**)&xg, g_x16);
    cudaGetSymbolAddress((void**)&wg, g_w16);
    cudaGetSymbolAddress((void**)&kg, g_k16);

    static bool attr_set = false;
    if (!attr_set) {
        cudaFuncSetAttribute(k_gemm_mma, cudaFuncAttributeMaxDynamicSharedMemorySize,
                             GEMM_SMEM_REQ);
        cudaFuncSetAttribute(hop_partial, cudaFuncAttributeMaxDynamicSharedMemorySize,
                             HOP_SMEM_);
        attr_set = true;
    }

    // convert: x, Wk -> fp16
    {
        int nch_x = (MROWS_ * C_) / 8;
        convert_fp16<<<(nch_x + 255) / 256, 256>>>(x, xg, nch_x);
        int nch_w = (C_ * C_) / 8;
        convert_fp16<<<(nch_w + 255) / 256, 256>>>(Wk, wg, nch_w);
    }
    // q0 = query @ Wq^T
    small_gemm_nt<<<dim3(C_ / 64, 1), 256>>>(query, Wq, nullptr, q0_scr, L_, C_, C_);
    // k = x @ Wk^T via single-term fp16 HMMA -> fp16 head-major
    k_gemm_mma<<<dim3(C_ / 128, MROWS_ / 128), GT_, GEMM_SMEM_REQ>>>(xg, wg, kg);
    // 3-step Hopfield attention (HMMA flash, NS=8 splits)
    hop_init_q<<<BH_, 256>>>(q0_scr, q_state);
    for (int s = 0; s < STEPS_; s++) {
        hop_partial<<<dim3(NS_, BH_), 256, HOP_SMEM_>>>(
            q_state, kg, m_part, z_part, acc_part);
        hop_combine<<<BH_, 256>>>(m_part, z_part, acc_part,
                                  (s == STEPS_ - 1) ? qf_scr : q_state,
                                  (s == STEPS_ - 1) ? 1 : 0);
    }
    // out projections
    small_gemm_nt<<<dim3(C_ / 64, (B_ * L_) / 16), 256>>>(
        qf_scr, Wv, nullptr, tmp_scr, B_ * L_, C_, C_);
    small_gemm_nt<<<dim3(C_ / 64, (B_ * L_) / 16), 256>>>(
        tmp_scr, Wproj, bproj, out, B_ * L_, C_, C_);
}